// round 15
// baseline (speedup 1.0000x reference)
#include <cuda_runtime.h>
#include <cuda_fp16.h>
#include <cstdint>

#define NB     16
#define NTAU   10
#define ND     6
#define NN     512
#define NW     9
#define NHID   64
#define KC     54
#define TILE_M 64
#define NTILE  128
#define TPB    256
#define DYN_BYTES (33792 + 128)

typedef unsigned long long ull;

// W0 pre-converted: [i*10+t] 8KB fp16 plane, swizzled [n][kk]
__device__ __align__(1024) unsigned char g_w0h[60 * 8192];

__device__ __forceinline__ uint32_t smem_u32(const void* p) {
    uint32_t a;
    asm("{ .reg .u64 t; cvta.to.shared.u64 t, %1; cvt.u32.u64 %0, t; }" : "=r"(a) : "l"(p));
    return a;
}
__device__ __forceinline__ ull ffma2(ull a, ull b, ull c) {
    ull d; asm("fma.rn.f32x2 %0, %1, %2, %3;" : "=l"(d) : "l"(a), "l"(b), "l"(c)); return d;
}
__device__ __forceinline__ ull pack2(float x) {
    ull d; asm("mov.b64 %0, {%1, %1};" : "=l"(d) : "f"(x)); return d;
}
__device__ __forceinline__ float2 unpack2(ull v) {
    float2 r; asm("mov.b64 {%0, %1}, %2;" : "=f"(r.x), "=f"(r.y) : "l"(v)); return r;
}
__device__ __forceinline__ uint32_t cvt_f16x2(float hi, float lo) {   // lo16 = lo
    uint32_t r; asm("cvt.rn.f16x2.f32 %0, %1, %2;" : "=r"(r) : "f"(hi), "f"(lo)); return r;
}
__device__ __forceinline__ float2 ldcs2(const float* p) {
    float2 r; asm volatile("ld.global.cs.v2.f32 {%0,%1}, [%2];" : "=f"(r.x), "=f"(r.y) : "l"(p)); return r;
}
__device__ __forceinline__ float4 ldcs4(const float* p) {
    float4 r; asm volatile("ld.global.cs.v4.f32 {%0,%1,%2,%3}, [%4];"
                           : "=f"(r.x), "=f"(r.y), "=f"(r.z), "=f"(r.w) : "l"(p));
    return r;
}
__device__ __forceinline__ void ldsm4(uint32_t a, uint32_t& r0, uint32_t& r1, uint32_t& r2, uint32_t& r3) {
    asm volatile("ldmatrix.sync.aligned.m8n8.x4.shared.b16 {%0,%1,%2,%3}, [%4];"
                 : "=r"(r0), "=r"(r1), "=r"(r2), "=r"(r3) : "r"(a));
}
__device__ __forceinline__ void mma_f16(float* d, uint32_t a0, uint32_t a1, uint32_t a2, uint32_t a3,
                                        uint32_t b0, uint32_t b1) {
    asm volatile("mma.sync.aligned.m16n8k16.row.col.f32.f16.f16.f32 "
                 "{%0,%1,%2,%3}, {%4,%5,%6,%7}, {%8,%9}, {%0,%1,%2,%3};"
                 : "+f"(d[0]), "+f"(d[1]), "+f"(d[2]), "+f"(d[3])
                 : "r"(a0), "r"(a1), "r"(a2), "r"(a3), "r"(b0), "r"(b1));
}
#define CP16(dst, src) asm volatile("cp.async.cg.shared.global [%0], [%1], 16;" :: "r"(dst), "l"(src))
#define CP_COMMIT()    asm volatile("cp.async.commit_group;" ::: "memory")
#define CP_WAIT0()     asm volatile("cp.async.wait_group 0;" ::: "memory")

// ------------ prep: W0 -> swizzled fp16 tile images (grid 60x4) ------------
__global__ void prep_w0(const float* __restrict__ W0)
{
    const int itx = blockIdx.x;                 // i*10 + t
    const int i = itx / 10, t = itx % 10;
    const float* src = W0 + ((size_t)i * 540 + t * KC) * NHID;
    unsigned char* dst = g_w0h + (size_t)itx * 8192;
    int e0 = blockIdx.y * 1024 + threadIdx.x;
    #pragma unroll
    for (int c = 0; c < 4; ++c) {
        int e = e0 + c * 256;
        int kk = e >> 6, n = e & 63;
        float v = (kk < KC) ? src[kk * 64 + n] : 0.f;
        uint32_t off = (uint32_t)(n * 128 + kk * 2) ^ ((uint32_t)(n & 7) << 4);
        *(uint16_t*)(dst + off) = __half_as_ushort(__float2half_rn(v));
    }
}

// ------------ fused: produce m in smem + fp16 tensor GEMM + layers 1/2 ------------
__global__ __launch_bounds__(TPB, 4)
void tsdcd_fused(const float* __restrict__ x,
                 const float* __restrict__ mask_param,
                 const float* __restrict__ u,
                 const float* __restrict__ b0,
                 const float* __restrict__ W1,
                 const float* __restrict__ b1,
                 const float* __restrict__ W2,
                 const float* __restrict__ b2,
                 float* __restrict__ out)
{
    extern __shared__ unsigned char dyn_raw[];
    __shared__ float E2_s[NTAU * 56];           // g-permuted, 16B-aligned rows
    __shared__ float x_s[2][6 * 12 * 17];
    __shared__ float b0_s[NHID], b1_s[NHID], W2_s[128], b2_s[2];
    __shared__ float2 po_s[TPB];

    const uint32_t raw_u = smem_u32(dyn_raw);
    const uint32_t dynb  = (raw_u + 127u) & ~127u;
    unsigned char* dyn = dyn_raw + (dynb - raw_u);
    // mainloop layout: A @0 (8K), B0 @8K, B1 @16K

    const int tid  = threadIdx.x;
    const int w    = tid >> 5;
    const int lane = tid & 31;
    const int i    = blockIdx.y;
    const int tile = blockIdx.x;
    const int tile0 = tile * TILE_M;
    const int n0    = tile0 >> 4;               // 4 n per tile
    const int kof   = (i & 1) ? 2 : 0;          // float4 group start (u alignment)
    const int kofl  = (i & 1) ? 0 : 52;         // leftover pair kk

    // ---- one-time staging ----
    {   // zero A tile (8KB): padding cols kk 54..63 MUST stay 0
        float4 z = make_float4(0.f, 0.f, 0.f, 0.f);
        float4* az = (float4*)dyn;
        #pragma unroll
        for (int e = tid; e < 512; e += TPB) az[e] = z;
    }
    for (int e = tid; e < NTAU * KC; e += TPB) {
        int t = e / KC, kk = e - t * KC;
        int g;
        if (kof == 0) g = kk;
        else          g = (kk >= 2) ? (kk - 2) : (52 + kk);
        E2_s[t * 56 + g] = __expf(-mask_param[(t * ND + i) * KC + kk]);
    }
    if (tid < NHID) { b0_s[tid] = b0[i * NHID + tid]; b1_s[tid] = b1[i * NHID + tid]; }
    if (tid < 128) W2_s[tid] = W2[i * 128 + tid];
    if (tid < 2)   b2_s[tid] = b2[i * 2 + tid];

    float d[4][4];
    #pragma unroll
    for (int q = 0; q < 4; ++q)
        #pragma unroll
        for (int c = 0; c < 4; ++c) d[q][c] = 0.f;

    // per-lane ldmatrix geometry (4 row-groups x 2 n-halves)
    const int rg = w & 3;
    const int nh = w >> 2;
    const int rowA = rg * 16 + (lane & 15);
    const uint32_t arow = (uint32_t)rowA * 128;
    const uint32_t axr  = (uint32_t)(rowA & 7) << 4;
    const uint32_t colsel = (uint32_t)(lane >> 4) << 4;

    // ---- helpers ----
    auto stage_x = [&](int t) {
        float* xb = x_s[t & 1];
        #pragma unroll
        for (int it = 0; it < 5; ++it) {
            int e = tid + it * 256;
            if (e < 1152) {
                int colw = e % 12;
                int j = (e / 12) % 6;
                int bb = e / 72;
                int col = n0 + colw - 4;
                float v = 0.f;
                if ((unsigned)col < NN) v = x[((bb * NTAU + t) * ND + j) * NN + col];
                xb[(j * 12 + colw) * 17 + bb] = v;
            }
        }
    };
    float4 ur4[4];
    float2 ur2;
    auto load_u = [&](int t) {
        const float* ub = u + (size_t)(t * ND + i) * KC;
        #pragma unroll
        for (int it = 0; it < 4; ++it) {
            int p = tid + it * 256;
            if (p < 832) {
                int r  = (p * 5042) >> 16;      // p/13
                int c4 = p - r * 13;
                ur4[it] = ldcs4(ub + (size_t)(tile0 + r) * 3240 + kof + 4 * c4);
            }
        }
        if (tid < 64)
            ur2 = ldcs2(ub + (size_t)(tile0 + tid) * 3240 + kofl);
    };
    auto cp_b = [&](int t) {
        const unsigned char* bsrc = g_w0h + (size_t)(i * 10 + t) * 8192;
        uint32_t bdst = dynb + 8192 + (uint32_t)(t & 1) * 8192;
        #pragma unroll
        for (int c = 0; c < 2; ++c)
            CP16(bdst + tid * 16 + c * 4096, bsrc + tid * 16 + c * 4096);
        CP_COMMIT();
    };
    auto do_math = [&](int t) {                 // m -> STS A (fp16x2)
        const float* xb = x_s[t & 1];
        const float* Et = E2_s + t * 56;
        #pragma unroll
        for (int it = 0; it < 4; ++it) {
            int p = tid + it * 256;
            if (p < 832) {
                int r  = (p * 5042) >> 16;
                int c4 = p - r * 13;
                int kk = kof + 4 * c4;
                float4 uv = ur4[it];
                float4 ev = *(const float4*)(Et + 4 * c4);
                int nl = r >> 4, bb = r & 15;
                float m[4];
                {
                    float uu[4] = {uv.x, uv.y, uv.z, uv.w};
                    float ee[4] = {ev.x, ev.y, ev.z, ev.w};
                    #pragma unroll
                    for (int e = 0; e < 4; ++e) {
                        int kke = kk + e;
                        int j = (kke * 57) >> 9;          // kke/9
                        float xv = xb[(kke + 3 * j + nl) * 17 + bb];
                        m[e] = xv * __fdividef(uu[e], fmaf(ee[e], 1.f - uu[e], uu[e]));
                    }
                }
                uint32_t h2a = cvt_f16x2(m[1], m[0]);
                uint32_t h2b = cvt_f16x2(m[3], m[2]);
                uint32_t key = (uint32_t)(r & 7) << 4;
                uint32_t ob  = (uint32_t)(r * 128 + 2 * kk);
                *(uint32_t*)(dyn + (ob ^ key))       = h2a;
                *(uint32_t*)(dyn + ((ob + 4) ^ key)) = h2b;
            }
        }
        if (tid < 64) {
            int r = tid;
            int nl = r >> 4, bb = r & 15;
            float2 uv = ur2;
            float2 ev = *(const float2*)(Et + 52);
            int k0 = kofl, k1 = kofl + 1;
            int j0 = (k0 * 57) >> 9, j1 = (k1 * 57) >> 9;
            float x0 = xb[(k0 + 3 * j0 + nl) * 17 + bb];
            float x1 = xb[(k1 + 3 * j1 + nl) * 17 + bb];
            float m0 = x0 * __fdividef(uv.x, fmaf(ev.x, 1.f - uv.x, uv.x));
            float m1 = x1 * __fdividef(uv.y, fmaf(ev.y, 1.f - uv.y, uv.y));
            uint32_t h2 = cvt_f16x2(m1, m0);
            uint32_t key = (uint32_t)(r & 7) << 4;
            *(uint32_t*)(dyn + (((uint32_t)(r * 128 + 2 * kofl)) ^ key)) = h2;
        }
    };
    auto consume = [&](int t) {
        uint32_t Abase = dynb;
        uint32_t Bbase = dynb + 8192 + (uint32_t)(t & 1) * 8192;
        #pragma unroll
        for (int k = 0; k < 4; ++k) {
            uint32_t colb = (uint32_t)k * 32 + colsel;
            uint32_t aa = Abase + arow + (colb ^ axr);
            uint32_t a0, a1, a2, a3;
            ldsm4(aa, a0, a1, a2, a3);
            #pragma unroll
            for (int g2 = 0; g2 < 2; ++g2) {
                int nrow = nh * 32 + g2 * 16 + (lane & 15);
                uint32_t ba = Bbase + (uint32_t)nrow * 128 + (colb ^ ((uint32_t)(nrow & 7) << 4));
                uint32_t b0r, b1r, b2r, b3r;
                ldsm4(ba, b0r, b1r, b2r, b3r);
                mma_f16(d[2 * g2],     a0, a1, a2, a3, b0r, b2r);
                mma_f16(d[2 * g2 + 1], a0, a1, a2, a3, b1r, b3r);
            }
        }
    };

    // ---- mainloop: 2 barriers / t; u reloaded in-place after consumption ----
    cp_b(0);
    stage_x(0);
    load_u(0);
    #pragma unroll 2
    for (int t = 0; t < NTAU; ++t) {
        CP_WAIT0();                    // B(t) resident
        __syncthreads();               // barrier1: x_s(t)/A free, B visible
        if (t + 1 < NTAU) {
            cp_b(t + 1);
            stage_x(t + 1);
        }
        do_math(t);
        if (t + 1 < NTAU) load_u(t + 1);
        __syncthreads();               // barrier2: A(t) visible
        consume(t);
    }
    __syncthreads();

    // ---- epilogue: bias+relu -> h_s (stride 68) @dyn+0; W1 @dyn+17408 ----
    {
        float* hs = (float*)dyn;
        int r0 = rg * 16 + (lane >> 2);
        int c0 = nh * 32 + 2 * (lane & 3);
        #pragma unroll
        for (int oct = 0; oct < 4; ++oct) {
            int c = c0 + 8 * oct;
            float ba = b0_s[c], bbv = b0_s[c + 1];
            *(float2*)&hs[r0 * 68 + c]       = make_float2(fmaxf(d[oct][0] + ba, 0.f), fmaxf(d[oct][1] + bbv, 0.f));
            *(float2*)&hs[(r0 + 8) * 68 + c] = make_float2(fmaxf(d[oct][2] + ba, 0.f), fmaxf(d[oct][3] + bbv, 0.f));
        }
        const unsigned char* w1src = (const unsigned char*)(W1 + (size_t)i * NHID * NHID);
        uint32_t w1dst = dynb + 17408;
        #pragma unroll
        for (int c = 0; c < 4; ++c)
            CP16(w1dst + tid * 16 + c * 4096, w1src + tid * 16 + c * 4096);
        CP_COMMIT();
        CP_WAIT0();
    }
    __syncthreads();

    // ---- layers 1+2: 4 threads/token, each a 16-wide g-slice ----
    {
        const float* hs  = (const float*)dyn;
        const float* W1s = (const float*)(dyn + 17408);
        int rloc = tid >> 2;
        int gq   = tid & 3;
        const float* hrow = hs + rloc * 68;
        ull acc2[8];
        #pragma unroll
        for (int p = 0; p < 8; ++p) acc2[p] = 0ULL;
        #pragma unroll 8
        for (int k = 0; k < NHID; ++k) {
            ull hdup = pack2(hrow[k]);
            const ulonglong2* wr = (const ulonglong2*)(W1s + k * NHID + gq * 16);
            #pragma unroll
            for (int q = 0; q < 4; ++q) {
                ulonglong2 wv = wr[q];
                acc2[2 * q]     = ffma2(hdup, wv.x, acc2[2 * q]);
                acc2[2 * q + 1] = ffma2(hdup, wv.y, acc2[2 * q + 1]);
            }
        }
        float o0 = 0.f, o1 = 0.f;
        #pragma unroll
        for (int p = 0; p < 8; ++p) {
            float2 v = unpack2(acc2[p]);
            int g0 = gq * 16 + 2 * p;
            float v0 = fmaxf(v.x + b1_s[g0], 0.f);
            float v1 = fmaxf(v.y + b1_s[g0 + 1], 0.f);
            o0 = fmaf(v0, W2_s[g0 * 2],     o0);
            o1 = fmaf(v0, W2_s[g0 * 2 + 1], o1);
            o0 = fmaf(v1, W2_s[g0 * 2 + 2], o0);
            o1 = fmaf(v1, W2_s[g0 * 2 + 3], o1);
        }
        po_s[tid] = make_float2(o0, o1);
    }
    __syncthreads();
    if (tid < TILE_M) {
        float2 a0 = po_s[4 * tid],     a1 = po_s[4 * tid + 1];
        float2 a2 = po_s[4 * tid + 2], a3 = po_s[4 * tid + 3];
        int token = tile0 + tid;
        int bb = token & (NB - 1);
        int nn = token >> 4;
        ((float2*)out)[(size_t)(bb * ND + i) * NN + nn] =
            make_float2(a0.x + a1.x + a2.x + a3.x + b2_s[0],
                        a0.y + a1.y + a2.y + a3.y + b2_s[1]);
    }
}

extern "C" void kernel_launch(void* const* d_in, const int* in_sizes, int n_in,
                              void* d_out, int out_size)
{
    const float* x  = (const float*)d_in[0];
    const float* mp = (const float*)d_in[1];
    const float* u  = (const float*)d_in[2];
    const float* W0 = (const float*)d_in[3];
    const float* b0 = (const float*)d_in[4];
    const float* W1 = (const float*)d_in[5];
    const float* b1 = (const float*)d_in[6];
    const float* W2 = (const float*)d_in[7];
    const float* b2 = (const float*)d_in[8];
    float* out = (float*)d_out;

    static int inited = 0;
    if (!inited) {
        cudaFuncSetAttribute(tsdcd_fused, cudaFuncAttributeMaxDynamicSharedMemorySize, DYN_BYTES);
        inited = 1;
    }
    prep_w0<<<dim3(60, 4), 256>>>(W0);
    tsdcd_fused<<<dim3(NTILE, ND), TPB, DYN_BYTES>>>(x, mp, u, b0, W1, b1, W2, b2, out);
}